// round 1
// baseline (speedup 1.0000x reference)
#include <cuda_runtime.h>
#include <cstdint>

// FracDownSample fused kernel (sm_103a).
// x:[16,256,128,128] f32, w_key:[64,256], w_sim:[4,64] -> out:[16,256,64,64] f32
// SI=4 (window), SO=2. 128%4==0 -> no padding; windows are disjoint.
//
// One CTA = (n, hb, wq): 4 pixel rows x 32 pixel cols = 128 pixels = 8 windows.
//  Phase 1: key GEMM [128 px x 256 ch] x [256 x 64] via tf32 mma.sync (HMMA).
//  Phase 2: kq = w_sim * relu(key) in registers + warp shuffle reduce.
//  Phase 3: per-window softmax over 16 positions (logits = kq/4).
//  Phase 4: out[c, window, q] = sum_p x[c,p] * a[p,q]  (x re-read, L2-hot).

#define H_ 128
#define W_ 128
#define C_ 256
#define KD 64
#define WS_STRIDE 260   // 64 x 260 tf32 w_key  (conflict-free B frags)
#define AS_STRIDE 136   // 2 x 16 x 136 tf32 x-chunk (conflict-free A frags)
#define KQ_STRIDE 5     // 128 x 5 f32 kq / softmax weights

__device__ __forceinline__ uint32_t f2tf(float f) {
    uint32_t r;
    asm("cvt.rna.tf32.f32 %0, %1;" : "=r"(r) : "f"(f));
    return r;
}

__global__ __launch_bounds__(256, 2)
void frac_downsample_kernel(const float* __restrict__ x,
                            const float* __restrict__ w_key,
                            const float* __restrict__ w_sim,
                            float* __restrict__ out) {
    extern __shared__ uint32_t smem[];
    uint32_t* Ws     = smem;                                   // 64*260
    uint32_t* As     = Ws + KD * WS_STRIDE;                    // 2*16*136
    float*    kqs    = (float*)(As + 2 * 16 * AS_STRIDE);      // 128*5
    float*    wsim_s = kqs + 128 * KQ_STRIDE;                  // 256

    const int tid = threadIdx.x;
    const int bid = blockIdx.x;
    const int n  = bid >> 7;          // 16
    const int hb = (bid >> 2) & 31;   // 32 window-rows
    const int wq = bid & 3;           // 4 col-quarters (8 windows each)

    // base of this CTA's pixel tile at channel 0: rows hb*4.., cols wq*32..
    const float* xbase = x + ((size_t)n * C_ * H_ + (size_t)hb * 4) * W_ + wq * 32;

    // ---- load full w_key (tf32) + w_sim into smem ----
    #pragma unroll 8
    for (int r = 0; r < 64; r++) {
        int idx = r * 256 + tid;                  // idx = key*256 + c
        Ws[(idx >> 8) * WS_STRIDE + (idx & 255)] = f2tf(w_key[idx]);
    }
    wsim_s[tid] = w_sim[tid];                     // [4][64] row-major

    // ---- stage channel-chunk 0 ----
    #pragma unroll
    for (int r = 0; r < 8; r++) {
        int idx = r * 256 + tid;
        int kk = idx >> 7, m = idx & 127;         // m = i*32 + j
        As[kk * AS_STRIDE + m] =
            f2tf(xbase[(size_t)kk * H_ * W_ + (m >> 5) * W_ + (m & 31)]);
    }
    __syncthreads();

    const int warp = tid >> 5, lane = tid & 31;
    const int gid = lane >> 2, tig = lane & 3;
    const int mbase = warp * 16;                  // rows [mbase, mbase+16)

    float acc[8][4];                              // 8 n-tiles of m16n8
    #pragma unroll
    for (int t = 0; t < 8; t++)
        acc[t][0] = acc[t][1] = acc[t][2] = acc[t][3] = 0.f;

    // ---- Phase 1: K-loop (double buffered) ----
    int buf = 0;
    for (int kc = 0; kc < 256; kc += 16) {
        float pre[8];
        const bool more = (kc + 16) < 256;
        if (more) {
            #pragma unroll
            for (int r = 0; r < 8; r++) {
                int idx = r * 256 + tid;
                int kk = idx >> 7, m = idx & 127;
                pre[r] = xbase[(size_t)(kc + 16 + kk) * H_ * W_ + (m >> 5) * W_ + (m & 31)];
            }
        }
        const uint32_t* Ac = As + buf * 16 * AS_STRIDE;
        #pragma unroll
        for (int ks = 0; ks < 16; ks += 8) {
            uint32_t a0 = Ac[(ks + tig)     * AS_STRIDE + mbase + gid];
            uint32_t a1 = Ac[(ks + tig)     * AS_STRIDE + mbase + gid + 8];
            uint32_t a2 = Ac[(ks + 4 + tig) * AS_STRIDE + mbase + gid];
            uint32_t a3 = Ac[(ks + 4 + tig) * AS_STRIDE + mbase + gid + 8];
            #pragma unroll
            for (int t = 0; t < 8; t++) {
                uint32_t b0 = Ws[(8 * t + gid) * WS_STRIDE + kc + ks + tig];
                uint32_t b1 = Ws[(8 * t + gid) * WS_STRIDE + kc + ks + 4 + tig];
                asm volatile(
                    "mma.sync.aligned.m16n8k8.row.col.f32.tf32.tf32.f32 "
                    "{%0,%1,%2,%3}, {%4,%5,%6,%7}, {%8,%9}, {%0,%1,%2,%3};"
                    : "+f"(acc[t][0]), "+f"(acc[t][1]), "+f"(acc[t][2]), "+f"(acc[t][3])
                    : "r"(a0), "r"(a1), "r"(a2), "r"(a3), "r"(b0), "r"(b1));
            }
        }
        if (more) {
            uint32_t* An = As + (buf ^ 1) * 16 * AS_STRIDE;
            #pragma unroll
            for (int r = 0; r < 8; r++) {
                int idx = r * 256 + tid;
                int kk = idx >> 7, m = idx & 127;
                An[kk * AS_STRIDE + m] = f2tf(pre[r]);
            }
        }
        __syncthreads();
        buf ^= 1;
    }

    // ---- Phase 2: kq = w_sim * relu(key), reduce over key-dim ----
    {
        const int r0 = mbase + gid, r1 = r0 + 8;
        float p0[4] = {0, 0, 0, 0}, p1[4] = {0, 0, 0, 0};
        #pragma unroll
        for (int t = 0; t < 8; t++) {
            int col0 = 8 * t + 2 * tig;
            float v0 = fmaxf(acc[t][0], 0.f);
            float v1 = fmaxf(acc[t][1], 0.f);
            float v2 = fmaxf(acc[t][2], 0.f);
            float v3 = fmaxf(acc[t][3], 0.f);
            #pragma unroll
            for (int s = 0; s < 4; s++) {
                float w0 = wsim_s[s * 64 + col0];
                float w1 = wsim_s[s * 64 + col0 + 1];
                p0[s] += v0 * w0 + v1 * w1;
                p1[s] += v2 * w0 + v3 * w1;
            }
        }
        #pragma unroll
        for (int s = 0; s < 4; s++) {
            p0[s] += __shfl_xor_sync(0xffffffffu, p0[s], 1);
            p0[s] += __shfl_xor_sync(0xffffffffu, p0[s], 2);
            p1[s] += __shfl_xor_sync(0xffffffffu, p1[s], 1);
            p1[s] += __shfl_xor_sync(0xffffffffu, p1[s], 2);
        }
        float w0v = (tig == 0) ? p0[0] : (tig == 1) ? p0[1] : (tig == 2) ? p0[2] : p0[3];
        float w1v = (tig == 0) ? p1[0] : (tig == 1) ? p1[1] : (tig == 2) ? p1[2] : p1[3];
        kqs[r0 * KQ_STRIDE + tig] = w0v;
        kqs[r1 * KQ_STRIDE + tig] = w1v;
    }
    __syncthreads();

    // ---- Phase 3: per-window softmax over 16 positions (logits = kq * 0.25) ----
    if (tid < 32) {
        int win = tid >> 2, s = tid & 3;
        float vals[16];
        float mx = -3.4e38f;
        #pragma unroll
        for (int p = 0; p < 16; p++) {
            int m = (p >> 2) * 32 + win * 4 + (p & 3);
            float v = kqs[m * KQ_STRIDE + s] * 0.25f;
            vals[p] = v;
            mx = fmaxf(mx, v);
        }
        float sum = 0.f;
        #pragma unroll
        for (int p = 0; p < 16; p++) { vals[p] = __expf(vals[p] - mx); sum += vals[p]; }
        float inv = 1.f / sum;
        #pragma unroll
        for (int p = 0; p < 16; p++) {
            int m = (p >> 2) * 32 + win * 4 + (p & 3);
            kqs[m * KQ_STRIDE + s] = vals[p] * inv;
        }
    }
    __syncthreads();

    // ---- Phase 4: aggregation (x re-read from L2) ----
    {
        const int win = tid & 7;          // window within CTA
        const int cb  = tid >> 3;         // channel offset 0..31
        const float* xa = x + (size_t)n * C_ * H_ * W_ + (size_t)(hb * 4) * W_
                          + wq * 32 + win * 4;
        float* ob = out + ((size_t)n * C_ * 64 + hb * 2) * 64 + wq * 16 + win * 2;
        #pragma unroll
        for (int pass = 0; pass < 8; pass++) {
            int c = pass * 32 + cb;
            const float* xp = xa + (size_t)c * H_ * W_;
            float o0 = 0.f, o1 = 0.f, o2 = 0.f, o3 = 0.f;
            #pragma unroll
            for (int i = 0; i < 4; i++) {
                float4 v = *reinterpret_cast<const float4*>(xp + i * W_);
                const float* ap = kqs + (i * 32 + win * 4) * KQ_STRIDE;
                o0 += v.x * ap[0];  o1 += v.x * ap[1];  o2 += v.x * ap[2];  o3 += v.x * ap[3];
                o0 += v.y * ap[5];  o1 += v.y * ap[6];  o2 += v.y * ap[7];  o3 += v.y * ap[8];
                o0 += v.z * ap[10]; o1 += v.z * ap[11]; o2 += v.z * ap[12]; o3 += v.z * ap[13];
                o0 += v.w * ap[15]; o1 += v.w * ap[16]; o2 += v.w * ap[17]; o3 += v.w * ap[18];
            }
            float* op = ob + (size_t)c * 64 * 64;
            *reinterpret_cast<float2*>(op)      = make_float2(o0, o1);  // row 2*hb
            *reinterpret_cast<float2*>(op + 64) = make_float2(o2, o3);  // row 2*hb+1
        }
    }
}

extern "C" void kernel_launch(void* const* d_in, const int* in_sizes, int n_in,
                              void* d_out, int out_size) {
    const float* x  = (const float*)d_in[0];
    const float* wk = (const float*)d_in[1];
    const float* ws = (const float*)d_in[2];
    float* out = (float*)d_out;

    const int smem_bytes = (KD * WS_STRIDE + 2 * 16 * AS_STRIDE) * 4
                         + (128 * KQ_STRIDE + 256) * 4;   // 87552 B
    cudaFuncSetAttribute(frac_downsample_kernel,
                         cudaFuncAttributeMaxDynamicSharedMemorySize, smem_bytes);

    // grid: 16 n * 32 hb * 4 wq = 2048 CTAs
    frac_downsample_kernel<<<2048, 256, smem_bytes>>>(x, wk, ws, out);
}

// round 2
// speedup vs baseline: 1.0631x; 1.0631x over previous
#include <cuda_runtime.h>
#include <cstdint>

// FracDownSample fused kernel v2 (sm_103a).
// x:[16,256,128,128] f32, w_key:[64,256], w_sim:[4,64] -> out:[16,256,64,64] f32
//
// One CTA = (n, hb, wq): 4 pixel rows x 32 cols = 128 pixels = 8 windows.
//  Phase 1: key GEMM [128 x 64 x 256] tf32 mma. Warps tiled m32 x n32
//           (4 m-warps x 2 n-warps). A & B in fragment-packed smem -> LDS.64.
//  Phase 2: kq = w_sim * relu(key), warp shuffle + 2-plane smem reduce.
//  Phase 3: per-window softmax over 16 positions.
//  Phase 4: aggregation, x re-read (L2-hot).

#define H_ 128
#define W_ 128
#define C_ 256
#define HW (H_ * W_)
#define KQ_STRIDE 5

#define BP_WORDS  16384          // 32 ksteps * 8 ntiles * 64 words
#define ACH_WORDS 2048           // 8 mtiles * 2 ks * 128 words (one 16-k chunk)

__device__ __forceinline__ uint32_t f2tf(float f) {
    uint32_t r;
    asm("cvt.rna.tf32.f32 %0, %1;" : "=r"(r) : "f"(f));
    return r;
}

// packed A position for (kk in 0..15, m in 0..127)
__device__ __forceinline__ int a_pos(int kk, int m) {
    int mt = m >> 4, ml = m & 15;
    int gid = ml & 7, b1 = ml >> 3;
    int ks = kk >> 3, kl = kk & 7;
    int tig = kl & 3, b2 = kl >> 2;
    return (mt * 2 + ks) * 128 + b2 * 64 + (gid * 4 + tig) * 2 + b1;
}

__global__ __launch_bounds__(256, 2)
void frac_downsample_kernel(const float* __restrict__ x,
                            const float* __restrict__ w_key,
                            const float* __restrict__ w_sim,
                            float* __restrict__ out) {
    extern __shared__ uint32_t smem[];
    uint32_t* Bp     = smem;                          // 16384 w  (64 KB)
    uint32_t* As     = Bp + BP_WORDS;                 // 2*2048 w (16 KB)
    float*    kq2    = (float*)(As + 2 * ACH_WORDS);  // 2 planes * 128*5
    float*    wsim_s = kq2 + 2 * 128 * KQ_STRIDE;     // 256

    const int tid = threadIdx.x;
    const int bid = blockIdx.x;
    const int n  = bid >> 7;
    const int hb = (bid >> 2) & 31;
    const int wq = bid & 3;

    const float* xbase = x + ((size_t)n * C_ * H_ + (size_t)hb * 4) * W_ + wq * 32;

    // ---- stage B (w_key) into fragment-packed smem, tf32 ----
    {
        const int ksg = tid >> 3;
        const int tig = tid & 3;
        const int b2  = (tid >> 2) & 1;
        #pragma unroll 8
        for (int r = 0; r < 64; r++) {
            int nt = r >> 3, g = r & 7;
            Bp[(ksg * 8 + nt) * 64 + (g * 4 + tig) * 2 + b2] = f2tf(w_key[r * 256 + tid]);
        }
    }
    wsim_s[tid] = w_sim[tid];

    // ---- per-thread staging offsets (constant across chunks) ----
    uint32_t rcoff[8];
    int      apos[8];
    #pragma unroll
    for (int r = 0; r < 8; r++) {
        int idx = r * 256 + tid;
        int kk = idx >> 7, m = idx & 127;
        rcoff[r] = kk * HW + (m >> 5) * W_ + (m & 31);
        apos[r]  = a_pos(kk, m);
    }

    // ---- stage A chunk 0 ----
    #pragma unroll
    for (int r = 0; r < 8; r++)
        As[apos[r]] = f2tf(xbase[rcoff[r]]);
    __syncthreads();

    const int warp = tid >> 5, lane = tid & 31;
    const int warp_m = warp & 3;          // 4 m-groups of 32 rows
    const int warp_n = warp >> 2;         // 2 n-groups of 32 keys
    const int gid = lane >> 2, tig = lane & 3;

    float acc[2][4][4];
    #pragma unroll
    for (int a = 0; a < 2; a++)
        #pragma unroll
        for (int b = 0; b < 4; b++)
            acc[a][b][0] = acc[a][b][1] = acc[a][b][2] = acc[a][b][3] = 0.f;

    // ---- Phase 1: K-loop, double-buffered 16-channel chunks ----
    int buf = 0;
    const float* xk = xbase + 16 * HW;    // next-chunk base
    for (int kc16 = 0; kc16 < 16; kc16++) {
        float pre[8];
        const bool more = kc16 < 15;
        if (more) {
            #pragma unroll
            for (int r = 0; r < 8; r++)
                pre[r] = xk[rcoff[r]];
        }
        const uint32_t* Ac = As + buf * ACH_WORDS;
        #pragma unroll
        for (int ks = 0; ks < 2; ks++) {
            const int ksg = kc16 * 2 + ks;
            uint2 alo[2], ahi[2];
            #pragma unroll
            for (int mtl = 0; mtl < 2; mtl++) {
                const uint32_t* ab = Ac + ((warp_m * 2 + mtl) * 2 + ks) * 128 + lane * 2;
                alo[mtl] = *reinterpret_cast<const uint2*>(ab);
                ahi[mtl] = *reinterpret_cast<const uint2*>(ab + 64);
            }
            uint2 bf[4];
            #pragma unroll
            for (int ntl = 0; ntl < 4; ntl++)
                bf[ntl] = *reinterpret_cast<const uint2*>(
                    Bp + (ksg * 8 + warp_n * 4 + ntl) * 64 + lane * 2);
            #pragma unroll
            for (int mtl = 0; mtl < 2; mtl++)
                #pragma unroll
                for (int ntl = 0; ntl < 4; ntl++) {
                    asm volatile(
                        "mma.sync.aligned.m16n8k8.row.col.f32.tf32.tf32.f32 "
                        "{%0,%1,%2,%3}, {%4,%5,%6,%7}, {%8,%9}, {%0,%1,%2,%3};"
                        : "+f"(acc[mtl][ntl][0]), "+f"(acc[mtl][ntl][1]),
                          "+f"(acc[mtl][ntl][2]), "+f"(acc[mtl][ntl][3])
                        : "r"(alo[mtl].x), "r"(alo[mtl].y),
                          "r"(ahi[mtl].x), "r"(ahi[mtl].y),
                          "r"(bf[ntl].x), "r"(bf[ntl].y));
                }
        }
        if (more) {
            uint32_t* An = As + (buf ^ 1) * ACH_WORDS;
            #pragma unroll
            for (int r = 0; r < 8; r++)
                An[apos[r]] = f2tf(pre[r]);
            xk += 16 * HW;
        }
        __syncthreads();
        buf ^= 1;
    }

    // ---- Phase 2: kq = w_sim * relu(key); reduce tig via shuffle,
    //      warp_n via two smem planes ----
    #pragma unroll
    for (int mtl = 0; mtl < 2; mtl++) {
        float pa[4] = {0, 0, 0, 0}, pb[4] = {0, 0, 0, 0};
        #pragma unroll
        for (int ntl = 0; ntl < 4; ntl++) {
            int col0 = warp_n * 32 + ntl * 8 + 2 * tig;
            float v0 = fmaxf(acc[mtl][ntl][0], 0.f);
            float v1 = fmaxf(acc[mtl][ntl][1], 0.f);
            float v2 = fmaxf(acc[mtl][ntl][2], 0.f);
            float v3 = fmaxf(acc[mtl][ntl][3], 0.f);
            #pragma unroll
            for (int s = 0; s < 4; s++) {
                float w0 = wsim_s[s * 64 + col0];
                float w1 = wsim_s[s * 64 + col0 + 1];
                pa[s] += v0 * w0 + v1 * w1;
                pb[s] += v2 * w0 + v3 * w1;
            }
        }
        #pragma unroll
        for (int s = 0; s < 4; s++) {
            pa[s] += __shfl_xor_sync(0xffffffffu, pa[s], 1);
            pa[s] += __shfl_xor_sync(0xffffffffu, pa[s], 2);
            pb[s] += __shfl_xor_sync(0xffffffffu, pb[s], 1);
            pb[s] += __shfl_xor_sync(0xffffffffu, pb[s], 2);
        }
        float va = (tig == 0) ? pa[0] : (tig == 1) ? pa[1] : (tig == 2) ? pa[2] : pa[3];
        float vb = (tig == 0) ? pb[0] : (tig == 1) ? pb[1] : (tig == 2) ? pb[2] : pb[3];
        int r0 = warp_m * 32 + mtl * 16 + gid;
        float* plane = kq2 + warp_n * 128 * KQ_STRIDE;
        plane[r0 * KQ_STRIDE + tig]       = va;
        plane[(r0 + 8) * KQ_STRIDE + tig] = vb;
    }
    __syncthreads();

    // ---- Phase 3: per-window softmax over 16 positions ----
    if (tid < 32) {
        int win = tid >> 2, s = tid & 3;
        float vals[16];
        float mx = -3.4e38f;
        #pragma unroll
        for (int p = 0; p < 16; p++) {
            int m = (p >> 2) * 32 + win * 4 + (p & 3);
            float v = (kq2[m * KQ_STRIDE + s] +
                       kq2[128 * KQ_STRIDE + m * KQ_STRIDE + s]) * 0.25f;
            vals[p] = v;
            mx = fmaxf(mx, v);
        }
        float sum = 0.f;
        #pragma unroll
        for (int p = 0; p < 16; p++) { vals[p] = __expf(vals[p] - mx); sum += vals[p]; }
        float inv = 1.f / sum;
        #pragma unroll
        for (int p = 0; p < 16; p++) {
            int m = (p >> 2) * 32 + win * 4 + (p & 3);
            kq2[m * KQ_STRIDE + s] = vals[p] * inv;
        }
    }
    __syncthreads();

    // ---- Phase 4: aggregation (x re-read from L2) ----
    {
        const float* kqs = kq2;          // plane 0 now holds final weights
        const int win = tid & 7;
        const int cb  = tid >> 3;
        const float* xa = x + (size_t)n * C_ * HW + (size_t)(hb * 4) * W_
                          + wq * 32 + win * 4;
        float* ob = out + ((size_t)n * C_ * 64 + hb * 2) * 64 + wq * 16 + win * 2;
        #pragma unroll
        for (int pass = 0; pass < 8; pass++) {
            int c = pass * 32 + cb;
            const float* xp = xa + (size_t)c * HW;
            float o0 = 0.f, o1 = 0.f, o2 = 0.f, o3 = 0.f;
            #pragma unroll
            for (int i = 0; i < 4; i++) {
                float4 v = *reinterpret_cast<const float4*>(xp + i * W_);
                const float* ap = kqs + (i * 32 + win * 4) * KQ_STRIDE;
                o0 += v.x * ap[0];  o1 += v.x * ap[1];  o2 += v.x * ap[2];  o3 += v.x * ap[3];
                o0 += v.y * ap[5];  o1 += v.y * ap[6];  o2 += v.y * ap[7];  o3 += v.y * ap[8];
                o0 += v.z * ap[10]; o1 += v.z * ap[11]; o2 += v.z * ap[12]; o3 += v.z * ap[13];
                o0 += v.w * ap[15]; o1 += v.w * ap[16]; o2 += v.w * ap[17]; o3 += v.w * ap[18];
            }
            float* op = ob + (size_t)c * 64 * 64;
            *reinterpret_cast<float2*>(op)      = make_float2(o0, o1);
            *reinterpret_cast<float2*>(op + 64) = make_float2(o2, o3);
        }
    }
}

extern "C" void kernel_launch(void* const* d_in, const int* in_sizes, int n_in,
                              void* d_out, int out_size) {
    const float* x  = (const float*)d_in[0];
    const float* wk = (const float*)d_in[1];
    const float* ws = (const float*)d_in[2];
    float* out = (float*)d_out;

    const int smem_bytes = (BP_WORDS + 2 * ACH_WORDS) * 4
                         + (2 * 128 * KQ_STRIDE + 256) * 4;   // 88064 B
    cudaFuncSetAttribute(frac_downsample_kernel,
                         cudaFuncAttributeMaxDynamicSharedMemorySize, smem_bytes);

    frac_downsample_kernel<<<2048, 256, smem_bytes>>>(x, wk, ws, out);
}

// round 4
// speedup vs baseline: 1.4310x; 1.3461x over previous
#include <cuda_runtime.h>
#include <cuda_bf16.h>
#include <cstdint>

// FracDownSample fused kernel v3 (sm_103a) — bf16 GEMM, 3 CTAs/SM.
// x:[16,256,128,128] f32, w_key:[64,256], w_sim:[4,64] -> out:[16,256,64,64] f32
//
// One CTA = (n, hb, wq): 4 pixel rows x 32 cols = 128 pixels = 8 windows.
//  Phase 1: key GEMM [128 x 64 x 256] bf16 mma.m16n8k16. Warp tiles m32 x n32.
//           A & B fragment-packed in smem (LDS.64, conflict-free reads).
//           Chunk = 16 channels = 1 kstep; LDG prefetch distance = 1 iteration.
//  Phase 2: kq = w_sim * relu(key), shuffle + 2-plane smem reduce.
//  Phase 3: per-window softmax over 16 positions.
//  Phase 4: aggregation in f32, x re-read (L2-hot).

#define H_ 128
#define W_ 128
#define C_ 256
#define HW (H_ * W_)
#define KQ_STRIDE 5

#define BP_WORDS  8192           // 16 ksteps * 8 ntiles * 64 words (bf16x2)
#define ACH_WORDS 1024           // 8 mtiles * 128 words per 16-ch chunk

__device__ __forceinline__ uint32_t packbf(float lo, float hi) {
    __nv_bfloat162 v = __floats2bfloat162_rn(lo, hi);   // x=lo(low half), y=hi
    return *reinterpret_cast<uint32_t*>(&v);
}

__global__ __launch_bounds__(256, 3)
void frac_downsample_kernel(const float* __restrict__ x,
                            const float* __restrict__ w_key,
                            const float* __restrict__ w_sim,
                            float* __restrict__ out) {
    extern __shared__ uint32_t smem[];
    uint32_t* Bp     = smem;                          // 8192 w (32 KB)
    uint32_t* As     = Bp + BP_WORDS;                 // 2*1024 w (8 KB)
    float*    kq2    = (float*)(As + 2 * ACH_WORDS);  // 2 planes * 128*5
    float*    wsim_s = kq2 + 2 * 128 * KQ_STRIDE;     // 256

    const int tid = threadIdx.x;
    const int bid = blockIdx.x;
    const int n  = bid >> 7;
    const int hb = (bid >> 2) & 31;
    const int wq = bid & 3;

    const float* xbase = x + ((size_t)n * C_ * H_ + (size_t)hb * 4) * W_ + wq * 32;

    // ---- stage B (w_key) fragment-packed bf16x2 ----
    {
        const int c    = (tid & 127) * 2;       // even channel
        const int s    = c >> 4;                // kstep
        const int kkc  = c & 15;
        const int tigc = (kkc >> 1) & 3;
        const int kh   = kkc >> 3;
        const int rb   = tid >> 7;
        #pragma unroll 8
        for (int rr = 0; rr < 32; rr++) {
            int r = rr * 2 + rb;
            int nt = r >> 3, g = r & 7;
            Bp[(s * 8 + nt) * 64 + (g * 4 + tigc) * 2 + kh] =
                packbf(w_key[r * 256 + c], w_key[r * 256 + c + 1]);
        }
    }
    wsim_s[tid] = w_sim[tid];

    // ---- per-thread A staging offsets (constant across chunks) ----
    // thread owns pixel m = tid&127, channel pairs kk = 4i + 2h, h = tid>>7.
    const int m  = tid & 127;
    const int h  = tid >> 7;
    const uint32_t pixoff = (uint32_t)(m >> 5) * W_ + (m & 31);
    uint32_t goff[4];
    int      sw[4];
    {
        const int mtile = m >> 4, ml = m & 15;
        const int gid_s = ml & 7, b1 = ml >> 3;
        #pragma unroll
        for (int i = 0; i < 4; i++) {
            int kkp = 2 * i + h;                       // kk = 2*kkp
            int tig_s = kkp & 3, kh_s = kkp >> 2;
            int lane_r = ((gid_s * 4 + tig_s) + mtile * 2) & 31;
            sw[i]   = mtile * 128 + kh_s * 64 + lane_r * 2 + b1;
            goff[i] = (uint32_t)(4 * i + 2 * h) * HW + pixoff;
        }
    }

    // ---- prologue: chunk 0 direct, chunk 1 into prefetch regs ----
    float pre[8];
    #pragma unroll
    for (int i = 0; i < 4; i++)
        As[sw[i]] = packbf(xbase[goff[i]], xbase[goff[i] + HW]);
    {
        const float* xc = xbase + 16 * HW;
        #pragma unroll
        for (int i = 0; i < 4; i++) {
            pre[2 * i]     = xc[goff[i]];
            pre[2 * i + 1] = xc[goff[i] + HW];
        }
    }
    __syncthreads();

    const int warp = tid >> 5, lane = tid & 31;
    const int warp_m = warp & 3;              // 4 m-groups of 32 rows
    const int warp_n = warp >> 2;             // 2 n-groups of 32 keys
    const int gid = lane >> 2, tig = lane & 3;

    float acc[2][4][4];
    #pragma unroll
    for (int a = 0; a < 2; a++)
        #pragma unroll
        for (int b = 0; b < 4; b++)
            acc[a][b][0] = acc[a][b][1] = acc[a][b][2] = acc[a][b][3] = 0.f;

    // ---- Phase 1: 16 ksteps, prefetch distance = 1 iteration ----
    for (int c = 0; c < 16; c++) {
        if (c + 1 < 16) {
            uint32_t* An = As + ((c + 1) & 1) * ACH_WORDS;
            #pragma unroll
            for (int i = 0; i < 4; i++)
                An[sw[i]] = packbf(pre[2 * i], pre[2 * i + 1]);
        }
        if (c + 2 < 16) {
            const float* xn = xbase + (size_t)(c + 2) * 16 * HW;
            #pragma unroll
            for (int i = 0; i < 4; i++) {
                pre[2 * i]     = xn[goff[i]];
                pre[2 * i + 1] = xn[goff[i] + HW];
            }
        }
        const uint32_t* Ac = As + (c & 1) * ACH_WORDS;
        uint2 afr[2][2];
        #pragma unroll
        for (int mtl = 0; mtl < 2; mtl++) {
            int mt = warp_m * 2 + mtl;
            int lr = ((lane + mt * 2) & 31) * 2;
            afr[mtl][0] = *reinterpret_cast<const uint2*>(Ac + mt * 128 + lr);
            afr[mtl][1] = *reinterpret_cast<const uint2*>(Ac + mt * 128 + 64 + lr);
        }
        uint2 bfr[4];
        #pragma unroll
        for (int ntl = 0; ntl < 4; ntl++)
            bfr[ntl] = *reinterpret_cast<const uint2*>(
                Bp + (c * 8 + warp_n * 4 + ntl) * 64 + lane * 2);
        #pragma unroll
        for (int mtl = 0; mtl < 2; mtl++)
            #pragma unroll
            for (int ntl = 0; ntl < 4; ntl++) {
                asm volatile(
                    "mma.sync.aligned.m16n8k16.row.col.f32.bf16.bf16.f32 "
                    "{%0,%1,%2,%3}, {%4,%5,%6,%7}, {%8,%9}, {%0,%1,%2,%3};"
                    : "+f"(acc[mtl][ntl][0]), "+f"(acc[mtl][ntl][1]),
                      "+f"(acc[mtl][ntl][2]), "+f"(acc[mtl][ntl][3])
                    : "r"(afr[mtl][0].x), "r"(afr[mtl][0].y),
                      "r"(afr[mtl][1].x), "r"(afr[mtl][1].y),
                      "r"(bfr[ntl].x), "r"(bfr[ntl].y));
            }
        __syncthreads();
    }

    // ---- Phase 2: kq = w_sim * relu(key); reduce tig via shuffle,
    //      warp_n via two smem planes ----
    #pragma unroll
    for (int mtl = 0; mtl < 2; mtl++) {
        float pa[4] = {0, 0, 0, 0}, pb[4] = {0, 0, 0, 0};
        #pragma unroll
        for (int ntl = 0; ntl < 4; ntl++) {
            int col0 = warp_n * 32 + ntl * 8 + 2 * tig;
            float v0 = fmaxf(acc[mtl][ntl][0], 0.f);
            float v1 = fmaxf(acc[mtl][ntl][1], 0.f);
            float v2 = fmaxf(acc[mtl][ntl][2], 0.f);
            float v3 = fmaxf(acc[mtl][ntl][3], 0.f);
            #pragma unroll
            for (int s = 0; s < 4; s++) {
                float w0 = wsim_s[s * 64 + col0];
                float w1 = wsim_s[s * 64 + col0 + 1];
                pa[s] += v0 * w0 + v1 * w1;
                pb[s] += v2 * w0 + v3 * w1;
            }
        }
        #pragma unroll
        for (int s = 0; s < 4; s++) {
            pa[s] += __shfl_xor_sync(0xffffffffu, pa[s], 1);
            pa[s] += __shfl_xor_sync(0xffffffffu, pa[s], 2);
            pb[s] += __shfl_xor_sync(0xffffffffu, pb[s], 1);
            pb[s] += __shfl_xor_sync(0xffffffffu, pb[s], 2);
        }
        float va = (tig == 0) ? pa[0] : (tig == 1) ? pa[1] : (tig == 2) ? pa[2] : pa[3];
        float vb = (tig == 0) ? pb[0] : (tig == 1) ? pb[1] : (tig == 2) ? pb[2] : pb[3];
        int r0 = warp_m * 32 + mtl * 16 + gid;
        float* plane = kq2 + warp_n * 128 * KQ_STRIDE;
        plane[r0 * KQ_STRIDE + tig]       = va;
        plane[(r0 + 8) * KQ_STRIDE + tig] = vb;
    }
    __syncthreads();

    // ---- Phase 3: per-window softmax over 16 positions ----
    if (tid < 32) {
        int win = tid >> 2, s = tid & 3;
        float vals[16];
        float mx = -3.4e38f;
        #pragma unroll
        for (int p = 0; p < 16; p++) {
            int mm = (p >> 2) * 32 + win * 4 + (p & 3);
            float v = (kq2[mm * KQ_STRIDE + s] +
                       kq2[128 * KQ_STRIDE + mm * KQ_STRIDE + s]) * 0.25f;
            vals[p] = v;
            mx = fmaxf(mx, v);
        }
        float sum = 0.f;
        #pragma unroll
        for (int p = 0; p < 16; p++) { vals[p] = __expf(vals[p] - mx); sum += vals[p]; }
        float inv = 1.f / sum;
        #pragma unroll
        for (int p = 0; p < 16; p++) {
            int mm = (p >> 2) * 32 + win * 4 + (p & 3);
            kq2[mm * KQ_STRIDE + s] = vals[p] * inv;
        }
    }
    __syncthreads();

    // ---- Phase 4: aggregation in f32 (x re-read from L2) ----
    {
        const float* kqs = kq2;           // plane 0 holds final weights
        const int win = tid & 7;
        const int cb  = tid >> 3;
        const float* xa = x + (size_t)n * C_ * HW + (size_t)(hb * 4) * W_
                          + wq * 32 + win * 4;
        float* ob = out + ((size_t)n * C_ * 64 + hb * 2) * 64 + wq * 16 + win * 2;
        #pragma unroll
        for (int pass = 0; pass < 8; pass++) {
            int c = pass * 32 + cb;
            const float* xp = xa + (size_t)c * HW;
            float o0 = 0.f, o1 = 0.f, o2 = 0.f, o3 = 0.f;
            #pragma unroll
            for (int i = 0; i < 4; i++) {
                float4 v = *reinterpret_cast<const float4*>(xp + i * W_);
                const float* ap = kqs + (i * 32 + win * 4) * KQ_STRIDE;
                o0 += v.x * ap[0];  o1 += v.x * ap[1];  o2 += v.x * ap[2];  o3 += v.x * ap[3];
                o0 += v.y * ap[5];  o1 += v.y * ap[6];  o2 += v.y * ap[7];  o3 += v.y * ap[8];
                o0 += v.z * ap[10]; o1 += v.z * ap[11]; o2 += v.z * ap[12]; o3 += v.z * ap[13];
                o0 += v.w * ap[15]; o1 += v.w * ap[16]; o2 += v.w * ap[17]; o3 += v.w * ap[18];
            }
            float* op = ob + (size_t)c * 64 * 64;
            *reinterpret_cast<float2*>(op)      = make_float2(o0, o1);
            *reinterpret_cast<float2*>(op + 64) = make_float2(o2, o3);
        }
    }
}

extern "C" void kernel_launch(void* const* d_in, const int* in_sizes, int n_in,
                              void* d_out, int out_size) {
    const float* x  = (const float*)d_in[0];
    const float* wk = (const float*)d_in[1];
    const float* ws = (const float*)d_in[2];
    float* out = (float*)d_out;

    const int smem_bytes = (BP_WORDS + 2 * ACH_WORDS) * 4
                         + (2 * 128 * KQ_STRIDE + 256) * 4;   // 47104 B
    cudaFuncSetAttribute(frac_downsample_kernel,
                         cudaFuncAttributeMaxDynamicSharedMemorySize, smem_bytes);

    frac_downsample_kernel<<<2048, 256, smem_bytes>>>(x, wk, ws, out);
}